// round 2
// baseline (speedup 1.0000x reference)
#include <cuda_runtime.h>
#include <math.h>

// Problem constants (fixed by the reference setup_inputs)
//   B=16, LL=257, D=64, H=128, lags=1  -> length=256, N=4096, in_dim=65
#define SLOPE 0.2f
#define EPSF  1e-8f

// Deterministic scratch for per-latent log|deriv| terms: [64][4096]
__device__ float g_scratch[64 * 4096];

// XOR swizzle at float4 granularity inside a 128-wide k-major tile.
// Returns float index for (row k, logical column m).
__device__ __forceinline__ int swz(int k, int m) {
    return (k << 7) + (((((m >> 2) ^ k) & 31) << 2) | (m & 3));
}

__global__ __launch_bounds__(256, 1)
void mlp_kernel(const float* __restrict__ x,
                const float* __restrict__ W1, const float* __restrict__ b1,
                const float* __restrict__ W2, const float* __restrict__ b2,
                const float* __restrict__ W3, const float* __restrict__ b3,
                const float* __restrict__ W4, const float* __restrict__ b4,
                float* __restrict__ out)
{
    extern __shared__ float sm[];
    float* sA = sm;            // activations, k-major [K][128]
    float* sD = sm + 16384;    // derivative chain, k-major [K][128]
    float* sW = sm + 32768;    // current layer weights, k-major [K][128]

    const int i   = blockIdx.y;        // latent index 0..63
    const int n0  = blockIdx.x << 7;   // row tile base (128 rows)
    const int tid = threadIdx.x;
    const int tx  = tid & 15, ty = tid >> 4;
    const int mb  = ty << 3,  jb = tx << 3;

    // ---- stage layer-1 inputs: inp[n][k], k in [0,65): 64 lag dims + x_t[i] ----
    for (int idx = tid; idx < 65 * 128; idx += 256) {
        int m = idx & 127, k = idx >> 7;
        int n = n0 + m;
        int xbase = ((n >> 8) * 257 + (n & 255)) << 6;   // (b*257 + t)*64
        sA[swz(k, m)] = (k < 64) ? x[xbase + k] : x[xbase + 64 + i];
    }
    // ---- stage W1[i] transposed to k-major [65][128] ----
    for (int idx = tid; idx < 128 * 65; idx += 256) {
        int j = idx / 65, k = idx - j * 65;
        sW[swz(k, j)] = W1[(i * 128 + j) * 65 + k];
    }
    __syncthreads();

    float accA[8][8], accD[8][8];
#pragma unroll
    for (int a = 0; a < 8; ++a)
#pragma unroll
        for (int b = 0; b < 8; ++b) accA[a][b] = 0.f;

    // ================= layer 1 GEMM (K=65, forward path only) =================
    for (int k = 0; k < 65; ++k) {
        float4 a0 = *(const float4*)(sA + swz(k, mb));
        float4 a1 = *(const float4*)(sA + swz(k, mb + 4));
        float4 w0 = *(const float4*)(sW + swz(k, jb));
        float4 w1 = *(const float4*)(sW + swz(k, jb + 4));
        float av[8] = {a0.x,a0.y,a0.z,a0.w,a1.x,a1.y,a1.z,a1.w};
        float wv[8] = {w0.x,w0.y,w0.z,w0.w,w1.x,w1.y,w1.z,w1.w};
#pragma unroll
        for (int mm = 0; mm < 8; ++mm)
#pragma unroll
            for (int jj = 0; jj < 8; ++jj)
                accA[mm][jj] += av[mm] * wv[jj];
    }
    __syncthreads();

    // layer-1 epilogue: bias + LeakyReLU, init d = s1 * W1[:, -1], write back k-major
#pragma unroll
    for (int jj = 0; jj < 8; ++jj) {
        int j = jb + jj;
        float bias  = b1[i * 128 + j];
        float wlast = W1[(i * 128 + j) * 65 + 64];
        float av[8], dv[8];
#pragma unroll
        for (int mm = 0; mm < 8; ++mm) {
            float p = accA[mm][jj] + bias;
            float s = (p > 0.f) ? 1.f : SLOPE;
            av[mm] = s * p;
            dv[mm] = s * wlast;
        }
        *(float4*)(sA + swz(j, mb))     = make_float4(av[0],av[1],av[2],av[3]);
        *(float4*)(sA + swz(j, mb + 4)) = make_float4(av[4],av[5],av[6],av[7]);
        *(float4*)(sD + swz(j, mb))     = make_float4(dv[0],dv[1],dv[2],dv[3]);
        *(float4*)(sD + swz(j, mb + 4)) = make_float4(dv[4],dv[5],dv[6],dv[7]);
    }
    // stage W2[i]
    for (int idx = tid; idx < 16384; idx += 256) {
        int j = idx >> 7, k = idx & 127;
        sW[swz(k, j)] = W2[(i * 128 + j) * 128 + k];
    }
    __syncthreads();

    // ================= layers 2 and 3: fused forward + derivative GEMMs =================
    for (int layer = 0; layer < 2; ++layer) {
        const float* bp = (layer == 0) ? b2 : b3;
#pragma unroll
        for (int a = 0; a < 8; ++a)
#pragma unroll
            for (int b = 0; b < 8; ++b) { accA[a][b] = 0.f; accD[a][b] = 0.f; }

        for (int k0 = 0; k0 < 32; ++k0) {
            int oa0 = swz(k0, mb), oa1 = swz(k0, mb + 4);
            int ow0 = swz(k0, jb), ow1 = swz(k0, jb + 4);
#pragma unroll
            for (int kk = 0; kk < 4; ++kk) {
                int off = kk << 12;   // +32 rows * 128 floats (swizzle repeats mod 32)
                float4 a0 = *(const float4*)(sA + oa0 + off);
                float4 a1 = *(const float4*)(sA + oa1 + off);
                float4 d0 = *(const float4*)(sD + oa0 + off);
                float4 d1 = *(const float4*)(sD + oa1 + off);
                float4 w0 = *(const float4*)(sW + ow0 + off);
                float4 w1 = *(const float4*)(sW + ow1 + off);
                float av[8] = {a0.x,a0.y,a0.z,a0.w,a1.x,a1.y,a1.z,a1.w};
                float dv[8] = {d0.x,d0.y,d0.z,d0.w,d1.x,d1.y,d1.z,d1.w};
                float wv[8] = {w0.x,w0.y,w0.z,w0.w,w1.x,w1.y,w1.z,w1.w};
#pragma unroll
                for (int mm = 0; mm < 8; ++mm)
#pragma unroll
                    for (int jj = 0; jj < 8; ++jj) {
                        accA[mm][jj] += av[mm] * wv[jj];
                        accD[mm][jj] += dv[mm] * wv[jj];
                    }
            }
        }
        __syncthreads();

#pragma unroll
        for (int jj = 0; jj < 8; ++jj) {
            int j = jb + jj;
            float bias = bp[i * 128 + j];
            float av[8], dv[8];
#pragma unroll
            for (int mm = 0; mm < 8; ++mm) {
                float p = accA[mm][jj] + bias;
                float s = (p > 0.f) ? 1.f : SLOPE;
                av[mm] = s * p;
                dv[mm] = s * accD[mm][jj];
            }
            *(float4*)(sA + swz(j, mb))     = make_float4(av[0],av[1],av[2],av[3]);
            *(float4*)(sA + swz(j, mb + 4)) = make_float4(av[4],av[5],av[6],av[7]);
            *(float4*)(sD + swz(j, mb))     = make_float4(dv[0],dv[1],dv[2],dv[3]);
            *(float4*)(sD + swz(j, mb + 4)) = make_float4(dv[4],dv[5],dv[6],dv[7]);
        }
        if (layer == 0) {
            for (int idx = tid; idx < 16384; idx += 256) {
                int j = idx >> 7, k = idx & 127;
                sW[swz(k, j)] = W3[(i * 128 + j) * 128 + k];
            }
        }
        __syncthreads();
    }

    // ================= layer 4: per-row dot with W4[i] (forward + deriv) =================
    {
        int m = tid >> 1, h = tid & 1;
        const float* w4 = W4 + i * 128 + (h << 6);
        float pa = 0.f, pd = 0.f;
#pragma unroll 8
        for (int jj = 0; jj < 64; ++jj) {
            int j = (h << 6) + jj;
            float w = w4[jj];
            int o = swz(j, m);
            pa += sA[o] * w;
            pd += sD[o] * w;
        }
        sW[tid]       = pa;   // sW free after layer 3; reuse as reduction scratch
        sW[256 + tid] = pd;
    }
    __syncthreads();
    if ((tid & 1) == 0) {
        int m = tid >> 1;
        float res = sW[tid] + sW[tid + 1] + b4[i];
        float der = sW[256 + tid] + sW[257 + tid];
        int n = n0 + m;
        out[(n << 6) + i] = res;                       // residuals[b][t][i]
        g_scratch[i * 4096 + n] = logf(fabsf(der) + EPSF);
    }
}

// Deterministic reduction over latents: log_abs_det[n] = sum_i log(|deriv|+eps)
__global__ void reduce_log_kernel(float* __restrict__ out) {
    int n = blockIdx.x * blockDim.x + threadIdx.x;
    if (n < 4096) {
        float s = 0.f;
#pragma unroll 8
        for (int i = 0; i < 64; ++i) s += g_scratch[i * 4096 + n];
        out[262144 + n] = s;   // after residuals [16*256*64]
    }
}

extern "C" void kernel_launch(void* const* d_in, const int* in_sizes, int n_in,
                              void* d_out, int out_size) {
    const float* x  = (const float*)d_in[0];
    const float* W1 = (const float*)d_in[1];
    const float* b1 = (const float*)d_in[2];
    const float* W2 = (const float*)d_in[3];
    const float* b2 = (const float*)d_in[4];
    const float* W3 = (const float*)d_in[5];
    const float* b3 = (const float*)d_in[6];
    const float* W4 = (const float*)d_in[7];
    const float* b4 = (const float*)d_in[8];
    float* out = (float*)d_out;

    // 3 x 128x128 fp32 tiles = 192 KB dynamic SMEM (opt-in; < 227 KB sm_103a cap)
    cudaFuncSetAttribute((const void*)mlp_kernel,
                         cudaFuncAttributeMaxDynamicSharedMemorySize, 196608);

    dim3 grid(32, 64);   // 32 row tiles x 64 latents
    mlp_kernel<<<grid, 256, 196608>>>(x, W1, b1, W2, b2, W3, b3, W4, b4, out);
    reduce_log_kernel<<<16, 256>>>(out);
}